// round 15
// baseline (speedup 1.0000x reference)
#include <cuda_runtime.h>
#include <cuda_fp16.h>
#include <math.h>

#define Bq 16
#define Hq 512
#define Nq 64
#define Lq 2048

// ---------------- scratch (device globals: no allocation allowed) ----------
__device__ __half g_yf[Bq * Hq * Lq];                // activations fp16 (32 MB)
__device__ __half g_Wh[Hq * Hq];                     // W fp16

// ---------------- f32x2 packed-math helpers --------------------------------
typedef unsigned long long u64;
__device__ __forceinline__ u64 pk2(float a, float b) {
    u64 r; asm("mov.b64 %0,{%1,%2};" : "=l"(r) : "f"(a), "f"(b)); return r;
}
__device__ __forceinline__ float2 upk2(u64 v) {
    float2 f; asm("mov.b64 {%0,%1},%2;" : "=f"(f.x), "=f"(f.y) : "l"(v)); return f;
}
__device__ __forceinline__ u64 ffma2(u64 a, u64 b, u64 c) {
    u64 d; asm("fma.rn.f32x2 %0,%1,%2,%3;" : "=l"(d) : "l"(a), "l"(b), "l"(c)); return d;
}
__device__ __forceinline__ u64 fmul2(u64 a, u64 b) {
    u64 d; asm("mul.rn.f32x2 %0,%1,%2;" : "=l"(d) : "l"(a), "l"(b)); return d;
}
__device__ __forceinline__ u64 fadd2(u64 a, u64 b) {
    u64 d; asm("add.rn.f32x2 %0,%1,%2;" : "=l"(d) : "l"(a), "l"(b)); return d;
}

// ---------------- kernel 1: scan (params fused) + skip + GELU --------------
// 16 lanes/seq, 4 modes/lane (2 f32x2 pairs), 8 seqs per 128-thread block,
// 1024 blocks (2x warp count vs 8-lane layout -> latency hiding).
// 2-step-blocked recurrence (identical math to round-14):
//   x' = w^2 x + w u1 + u2
//   y1 = Re(ccw  x) + (s0+D) u1
//   y2 = Re(ccw2 x) + s1 u1 + (s0+D) u2
// Deferred reduction: 4 timestep-partials (u64) reduce-scattered over the 16
// lanes once per 4 timesteps (xor 1,2 scatter + xor 4,8 butterfly).
#define MPL   4
#define SEQS  8
#define TCH   256
#define SPITCH 260

__global__ __launch_bounds__(128, 6) void scan_kernel(
        const float* __restrict__ u,
        const float* __restrict__ D,
        const float* __restrict__ log_dt,
        const float* __restrict__ A_re,
        const float* __restrict__ A_im,
        const float* __restrict__ C_re,
        const float* __restrict__ C_im,
        const float* __restrict__ W) {
    __shared__ float su[SEQS][SPITCH];
    __shared__ float sy[SEQS][SPITCH];

    int tid  = threadIdx.x;
    int grp  = tid >> 4;                 // 0..7 sequence within block
    int sub  = tid & 15;                 // 0..15 lane within sequence
    int gid0 = blockIdx.x * SEQS;
    int gid  = gid0 + grp;
    int h    = gid & (Hq - 1);

    // ---- fused W fp16 conversion: this block's 256-element slice ----------
    if (tid < 64) {
        size_t wo = (size_t)blockIdx.x * 256 + tid * 4;
        float4 wv = *(const float4*)(W + wo);
        __half2 a  = __floats2half2_rn(wv.x, wv.y);
        __half2 b2 = __floats2half2_rn(wv.z, wv.w);
        uint2 pkw;
        pkw.x = *(unsigned*)&a;
        pkw.y = *(unsigned*)&b2;
        *(uint2*)(g_Wh + wo) = pkw;
    }

    // ---- per-thread parameter computation (4 modes = 2 pairs) -------------
    u64 pw_re[2], pw_im[2], pw2_re[2], pw2_im[2], pnw2_im[2];
    u64 pccw_re[2], pnccw_im[2], pccw2_re[2], pnccw2_im[2];
    u64 xre2[2], xim2[2];
    float s0p = 0.0f, s1p = 0.0f;
    {
        float dt = expf(log_dt[h]);
        int base = h * Nq + sub * MPL;
#pragma unroll
        for (int p = 0; p < 2; p++) {
            float wreA[2], wimA[2], w2reA[2], w2imA[2];
            float cwreA[2], cwimA[2], cw2reA[2], cw2imA[2];
#pragma unroll
            for (int s = 0; s < 2; s++) {
                int idx = base + 2 * p + s;
                float ar = -expf(A_re[idx]);
                float ai = A_im[idx];
                float er = expf(dt * ar);
                float wre = er * cosf(dt * ai);
                float wim = er * sinf(dt * ai);
                float den = ar * ar + ai * ai;
                float numr = wre - 1.0f, numi = wim;
                float qre = (numr * ar + numi * ai) / den;
                float qim = (numi * ar - numr * ai) / den;
                float cr = C_re[idx], ci = C_im[idx];
                float ccre = 2.0f * (cr * qre - ci * qim);
                float ccim = 2.0f * (cr * qim + ci * qre);
                float ccwre = ccre * wre - ccim * wim;
                float ccwim = ccre * wim + ccim * wre;
                float w2re = wre * wre - wim * wim;
                float w2im = 2.0f * wre * wim;
                float ccw2re = ccwre * wre - ccwim * wim;
                float ccw2im = ccwre * wim + ccwim * wre;
                s0p += ccre;
                s1p += ccwre;
                wreA[s] = wre;   wimA[s] = wim;
                w2reA[s] = w2re; w2imA[s] = w2im;
                cwreA[s] = ccwre;  cwimA[s] = ccwim;
                cw2reA[s] = ccw2re; cw2imA[s] = ccw2im;
            }
            pw_re[p]     = pk2(wreA[0],  wreA[1]);
            pw_im[p]     = pk2(wimA[0],  wimA[1]);
            pw2_re[p]    = pk2(w2reA[0], w2reA[1]);
            pw2_im[p]    = pk2(w2imA[0], w2imA[1]);
            pnw2_im[p]   = pk2(-w2imA[0], -w2imA[1]);
            pccw_re[p]   = pk2(cwreA[0], cwreA[1]);
            pnccw_im[p]  = pk2(-cwimA[0], -cwimA[1]);
            pccw2_re[p]  = pk2(cw2reA[0], cw2reA[1]);
            pnccw2_im[p] = pk2(-cw2imA[0], -cw2imA[1]);
            xre2[p] = 0ull;
            xim2[p] = 0ull;
        }
    }
    // sum s0/s1 across the 16 lanes of this sequence
    s0p += __shfl_xor_sync(0xFFFFFFFFu, s0p, 1);
    s0p += __shfl_xor_sync(0xFFFFFFFFu, s0p, 2);
    s0p += __shfl_xor_sync(0xFFFFFFFFu, s0p, 4);
    s0p += __shfl_xor_sync(0xFFFFFFFFu, s0p, 8);
    s1p += __shfl_xor_sync(0xFFFFFFFFu, s1p, 1);
    s1p += __shfl_xor_sync(0xFFFFFFFFu, s1p, 2);
    s1p += __shfl_xor_sync(0xFFFFFFFFu, s1p, 4);
    s1p += __shfl_xor_sync(0xFFFFFFFFu, s1p, 8);
    float Ds0 = D[h] + s0p;
    // ts = ((sub&1)<<1) | ((sub>>1)&1); odd ts <=> (sub&2)
    int   ts  = ((sub & 1) << 1) | ((sub >> 1) & 1);
    int   tsm = ts ? ts - 1 : 0;
    float s1e = (sub & 2) ? s1p : 0.0f;

    const float* ub = u + (size_t)gid0 * Lq;

    for (int c0 = 0; c0 < Lq; c0 += TCH) {
#pragma unroll
        for (int it = 0; it < (SEQS * TCH / 4) / 128; it++) {
            int idx = tid + it * 128;
            int r   = idx >> 6;
            int c4  = idx & 63;
            float4 v = *(const float4*)(ub + (size_t)r * Lq + c0 + c4 * 4);
            *(float4*)&su[r][c4 * 4] = v;
        }
        __syncthreads();

        for (int t0 = 0; t0 < TCH; t0 += 4) {
            u64 acc0 = 0ull, acc1 = 0ull, acc2 = 0ull, acc3 = 0ull;
            // j = 0: timesteps t0, t0+1
            {
                float us1 = su[grp][t0];
                float us2 = su[grp][t0 + 1];
                u64 u1_2 = pk2(us1, us1);
                u64 u2_2 = pk2(us2, us2);
#pragma unroll
                for (int p = 0; p < 2; p++) {
                    u64 tre = ffma2(pw_re[p], u1_2, u2_2);
                    tre = ffma2(pw2_re[p],  xre2[p], tre);
                    tre = ffma2(pnw2_im[p], xim2[p], tre);
                    u64 tim = fmul2(pw2_im[p], xre2[p]);
                    tim = ffma2(pw2_re[p], xim2[p], tim);
                    tim = ffma2(pw_im[p],  u1_2,    tim);
                    acc0 = ffma2(pccw_re[p],   xre2[p], acc0);
                    acc0 = ffma2(pnccw_im[p],  xim2[p], acc0);
                    acc1 = ffma2(pccw2_re[p],  xre2[p], acc1);
                    acc1 = ffma2(pnccw2_im[p], xim2[p], acc1);
                    xre2[p] = tre;
                    xim2[p] = tim;
                }
            }
            // j = 1: timesteps t0+2, t0+3
            {
                float us1 = su[grp][t0 + 2];
                float us2 = su[grp][t0 + 3];
                u64 u1_2 = pk2(us1, us1);
                u64 u2_2 = pk2(us2, us2);
#pragma unroll
                for (int p = 0; p < 2; p++) {
                    u64 tre = ffma2(pw_re[p], u1_2, u2_2);
                    tre = ffma2(pw2_re[p],  xre2[p], tre);
                    tre = ffma2(pnw2_im[p], xim2[p], tre);
                    u64 tim = fmul2(pw2_im[p], xre2[p]);
                    tim = ffma2(pw2_re[p], xim2[p], tim);
                    tim = ffma2(pw_im[p],  u1_2,    tim);
                    acc2 = ffma2(pccw_re[p],   xre2[p], acc2);
                    acc2 = ffma2(pnccw_im[p],  xim2[p], acc2);
                    acc3 = ffma2(pccw2_re[p],  xre2[p], acc3);
                    acc3 = ffma2(pnccw2_im[p], xim2[p], acc3);
                    xre2[p] = tre;
                    xim2[p] = tim;
                }
            }
            // ---- reduce-scatter over 16 lanes (4 timesteps) ----
            // r1 (xor 1): lane keeps timesteps {0,1} if !(sub&1) else {2,3}
            bool b1 = (sub & 1) != 0;
            bool b2 = (sub & 2) != 0;
            u64 sA = b1 ? acc0 : acc2;
            u64 sB = b1 ? acc1 : acc3;
            u64 rA = __shfl_xor_sync(0xFFFFFFFFu, sA, 1);
            u64 rB = __shfl_xor_sync(0xFFFFFFFFu, sB, 1);
            u64 va = fadd2(b1 ? acc2 : acc0, rA);
            u64 vb = fadd2(b1 ? acc3 : acc1, rB);
            // r2 (xor 2): keep one timestep
            u64 s2 = b2 ? va : vb;
            u64 r2 = __shfl_xor_sync(0xFFFFFFFFu, s2, 2);
            u64 c  = fadd2(b2 ? vb : va, r2);
            // r3/r4: plain butterflies (same ts within xor-4/8 groups)
            c = fadd2(c, __shfl_xor_sync(0xFFFFFFFFu, c, 4));
            c = fadd2(c, __shfl_xor_sync(0xFFFFFFFFu, c, 8));
            float2 f = upk2(c);
            float v = f.x + f.y;
            float uo = su[grp][t0 + ts];
            float up = su[grp][t0 + tsm];
            float y  = fmaf(s1e, up, fmaf(Ds0, uo, v));
            float gel = 0.5f * y * (1.0f + erff(y * 0.70710678118654752f));
            sy[grp][t0 + ts] = gel;       // 4 redundant lanes write same value
        }
        __syncthreads();

        // store activations as fp16
#pragma unroll
        for (int it = 0; it < (SEQS * TCH / 4) / 128; it++) {
            int idx = tid + it * 128;
            int r   = idx >> 6;
            int c4  = idx & 63;
            float4 v = *(float4*)&sy[r][c4 * 4];
            __half2 p0 = __floats2half2_rn(v.x, v.y);
            __half2 p1 = __floats2half2_rn(v.z, v.w);
            uint2 pk;
            pk.x = *(unsigned*)&p0;
            pk.y = *(unsigned*)&p1;
            size_t off = (size_t)(gid0 + r) * Lq + c0 + c4 * 4;
            *(uint2*)(g_yf + off) = pk;
        }
        __syncthreads();
    }
}

// ---------------- kernel 2: fp16 1-term GEMM, GBK=64, 2-stage pipeline -----
// out[b] (512 x 2048) = W (512x512) @ Y[b] (512x2048) + bias
#define GBM 128
#define GBN 128
#define GBK 64
#define ASTR 72
#define BSTR 136
#define A_ELEMS (GBM * ASTR)
#define B_ELEMS (GBK * BSTR)
#define AOFF(st) ((st) * A_ELEMS * 2)
#define BOFF(st) (2 * A_ELEMS * 2 + (st) * B_ELEMS * 2)
#define SMEM_GEMM (2 * A_ELEMS * 2 + 2 * B_ELEMS * 2)

#define LDSM4(r0, r1, r2, r3, addr) \
    asm volatile("ldmatrix.sync.aligned.m8n8.x4.shared.b16 {%0,%1,%2,%3},[%4];" \
                 : "=r"(r0), "=r"(r1), "=r"(r2), "=r"(r3) : "r"(addr))
#define LDSM4T(r0, r1, r2, r3, addr) \
    asm volatile("ldmatrix.sync.aligned.m8n8.x4.trans.shared.b16 {%0,%1,%2,%3},[%4];" \
                 : "=r"(r0), "=r"(r1), "=r"(r2), "=r"(r3) : "r"(addr))
#define MMA16816(d, a, b0, b1) \
    asm volatile("mma.sync.aligned.m16n8k16.row.col.f32.f16.f16.f32 " \
                 "{%0,%1,%2,%3},{%4,%5,%6,%7},{%8,%9},{%0,%1,%2,%3};" \
                 : "+f"(d[0]), "+f"(d[1]), "+f"(d[2]), "+f"(d[3]) \
                 : "r"(a[0]), "r"(a[1]), "r"(a[2]), "r"(a[3]), "r"(b0), "r"(b1))
#define CPA16(dst, src) \
    asm volatile("cp.async.cg.shared.global [%0],[%1],16;" :: "r"(dst), "l"(src))

extern __shared__ char dsm[];

__device__ __forceinline__ unsigned smem_u32g(const void* p) {
    unsigned a;
    asm("{ .reg .u64 t; cvta.to.shared.u64 t, %1; cvt.u32.u64 %0, t; }"
        : "=r"(a) : "l"(p));
    return a;
}

__global__ __launch_bounds__(256, 2) void gemm_kernel(const float* __restrict__ bias,
                                                      float* __restrict__ out) {
    unsigned sb = smem_u32g(dsm);
    int b   = blockIdx.z;
    int v0  = blockIdx.y * GBM;
    int l0  = blockIdx.x * GBN;
    int tid = threadIdx.x;
    int lane = tid & 31;
    int wid  = tid >> 5;
    int wm = wid >> 1;
    int wn = wid & 1;

    float acc[2][8][4];
#pragma unroll
    for (int i = 0; i < 2; i++)
#pragma unroll
        for (int j = 0; j < 8; j++)
#pragma unroll
            for (int k = 0; k < 4; k++) acc[i][j][k] = 0.0f;

#define LOAD_TILE(k0, st) do {                                              \
    _Pragma("unroll")                                                       \
    for (int q = 0; q < 4; q++) {                                           \
        int idx = tid + q * 256;                                            \
        int r = idx >> 3, c = (idx & 7) * 8;                                \
        size_t src = (size_t)(v0 + r) * Hq + (k0) + c;                      \
        unsigned d = (unsigned)(r * ASTR + c) * 2;                          \
        CPA16(sb + AOFF(st) + d, g_Wh + src);                               \
    }                                                                       \
    _Pragma("unroll")                                                       \
    for (int q = 0; q < 4; q++) {                                           \
        int idx = tid + q * 256;                                            \
        int r = idx >> 4, c = (idx & 15) * 8;                               \
        size_t src = (size_t)(b * Hq + (k0) + r) * Lq + l0 + c;             \
        unsigned d = (unsigned)(r * BSTR + c) * 2;                          \
        CPA16(sb + BOFF(st) + d, g_yf + src);                               \
    }                                                                       \
} while (0)

    LOAD_TILE(0, 0);
    asm volatile("cp.async.commit_group;");
    LOAD_TILE(GBK, 1);
    asm volatile("cp.async.commit_group;");

    for (int ch = 0; ch < Hq / GBK; ch++) {
        int st = ch & 1;
        asm volatile("cp.async.wait_group 1;");
        __syncthreads();

        unsigned ah_base = sb + AOFF(st);
        unsigned bh_base = sb + BOFF(st);

#pragma unroll
        for (int ks = 0; ks < 4; ks++) {
            unsigned ah[2][4], bh[4][4];
#pragma unroll
            for (int mf = 0; mf < 2; mf++) {
                unsigned d = ((wm * 32 + mf * 16 + (lane & 15)) * ASTR
                              + ks * 16 + (lane >> 4) * 8) * 2;
                LDSM4(ah[mf][0], ah[mf][1], ah[mf][2], ah[mf][3], ah_base + d);
            }
#pragma unroll
            for (int j = 0; j < 4; j++) {
                unsigned d = ((ks * 16 + (lane & 15)) * BSTR
                              + wn * 64 + j * 16 + (lane >> 4) * 8) * 2;
                LDSM4T(bh[j][0], bh[j][1], bh[j][2], bh[j][3], bh_base + d);
            }
#pragma unroll
            for (int mf = 0; mf < 2; mf++)
#pragma unroll
                for (int n8 = 0; n8 < 8; n8++) {
                    int j = n8 >> 1, hi = (n8 & 1) * 2;
                    MMA16816(acc[mf][n8], ah[mf], bh[j][hi], bh[j][hi + 1]);
                }
        }
        __syncthreads();

        int knext = (ch + 2) * GBK;
        if (knext < Hq) {
            LOAD_TILE(knext, st);
        }
        asm volatile("cp.async.commit_group;");
    }

    // ---- epilogue: bias + store ----
    int tq = lane >> 2, tr = lane & 3;
#pragma unroll
    for (int mf = 0; mf < 2; mf++) {
        int v = v0 + wm * 32 + mf * 16 + tq;
        float bv0 = bias[v], bv1 = bias[v + 8];
#pragma unroll
        for (int n8 = 0; n8 < 8; n8++) {
            int l = l0 + wn * 64 + n8 * 8 + tr * 2;
            float2 s0, s1;
            s0.x = acc[mf][n8][0] + bv0; s0.y = acc[mf][n8][1] + bv0;
            s1.x = acc[mf][n8][2] + bv1; s1.y = acc[mf][n8][3] + bv1;
            *(float2*)(out + ((size_t)b * Hq + v) * Lq + l)     = s0;
            *(float2*)(out + ((size_t)b * Hq + v + 8) * Lq + l) = s1;
        }
    }
}

// ---------------- launch ----------------------------------------------------
extern "C" void kernel_launch(void* const* d_in, const int* in_sizes, int n_in,
                              void* d_out, int out_size) {
    (void)in_sizes; (void)n_in; (void)out_size;
    const float* u      = (const float*)d_in[0];
    const float* log_dt = (const float*)d_in[1];
    const float* A_re   = (const float*)d_in[2];
    const float* A_im   = (const float*)d_in[3];
    const float* C_re   = (const float*)d_in[4];
    const float* C_im   = (const float*)d_in[5];
    const float* D      = (const float*)d_in[6];
    const float* W      = (const float*)d_in[7];
    const float* bias   = (const float*)d_in[8];
    float* out = (float*)d_out;

    static int smem_set = 0;
    if (!smem_set) {
        cudaFuncSetAttribute(gemm_kernel,
                             cudaFuncAttributeMaxDynamicSharedMemorySize,
                             SMEM_GEMM);
        smem_set = 1;
    }

    scan_kernel<<<Bq * Hq / SEQS, 128>>>(u, D, log_dt, A_re, A_im, C_re, C_im, W);
    dim3 g(Lq / GBN, Hq / GBM, Bq);
    gemm_kernel<<<g, 256, SMEM_GEMM>>>(bias, out);
}

// round 16
// speedup vs baseline: 1.1938x; 1.1938x over previous
#include <cuda_runtime.h>
#include <cuda_fp16.h>
#include <math.h>

#define Bq 16
#define Hq 512
#define Nq 64
#define Lq 2048

// ---------------- scratch (device globals: no allocation allowed) ----------
__device__ __half g_yf[Bq * Hq * Lq];                // activations fp16 (32 MB)
__device__ __half g_Wh[Hq * Hq];                     // W fp16

// ---------------- f32x2 packed-math helpers --------------------------------
typedef unsigned long long u64;
__device__ __forceinline__ u64 pk2(float a, float b) {
    u64 r; asm("mov.b64 %0,{%1,%2};" : "=l"(r) : "f"(a), "f"(b)); return r;
}
__device__ __forceinline__ float2 upk2(u64 v) {
    float2 f; asm("mov.b64 {%0,%1},%2;" : "=f"(f.x), "=f"(f.y) : "l"(v)); return f;
}
__device__ __forceinline__ u64 ffma2(u64 a, u64 b, u64 c) {
    u64 d; asm("fma.rn.f32x2 %0,%1,%2,%3;" : "=l"(d) : "l"(a), "l"(b), "l"(c)); return d;
}
__device__ __forceinline__ u64 fmul2(u64 a, u64 b) {
    u64 d; asm("mul.rn.f32x2 %0,%1,%2;" : "=l"(d) : "l"(a), "l"(b)); return d;
}
__device__ __forceinline__ u64 fadd2(u64 a, u64 b) {
    u64 d; asm("add.rn.f32x2 %0,%1,%2;" : "=l"(d) : "l"(a), "l"(b)); return d;
}

// ---------------- kernel 1: scan (params fused) + skip + GELU --------------
// 8 lanes/seq, 8 modes/lane, 16 seq/block (round-14 proven layout).
// 2-step-blocked recurrence:
//   x' = w^2 x + w u1 + u2
//   y1 = Re(ccw  x) + (s0+D) u1
//   y2 = Re(ccw2 x) + s1 u1 + (s0+D) u2
// NEW: per 8-timestep group, phase 1 = 4 state/acc iterations (FMA2 only),
// phase 2 = 4 INDEPENDENT packed shfl-trees (va,vb packed in one u64) so the
// 3x26-cycle shfl chains overlap instead of serializing per iteration.
#define MPL   8
#define SEQS  16
#define TCH   256
#define SPITCH 260

__global__ __launch_bounds__(128, 4) void scan_kernel(
        const float* __restrict__ u,
        const float* __restrict__ D,
        const float* __restrict__ log_dt,
        const float* __restrict__ A_re,
        const float* __restrict__ A_im,
        const float* __restrict__ C_re,
        const float* __restrict__ C_im,
        const float* __restrict__ W) {
    __shared__ float su[SEQS][SPITCH];
    __shared__ float sy[SEQS][SPITCH];

    int tid  = threadIdx.x;
    int grp  = tid >> 3;
    int sub  = tid & 7;
    int gid0 = blockIdx.x * SEQS;
    int gid  = gid0 + grp;
    int h    = gid & (Hq - 1);

    // ---- fused W fp16 conversion: this block's 512-element slice ----------
    {
        size_t wo = (size_t)blockIdx.x * 512 + tid * 4;
        float4 wv = *(const float4*)(W + wo);
        __half2 a  = __floats2half2_rn(wv.x, wv.y);
        __half2 b2 = __floats2half2_rn(wv.z, wv.w);
        uint2 pkw;
        pkw.x = *(unsigned*)&a;
        pkw.y = *(unsigned*)&b2;
        *(uint2*)(g_Wh + wo) = pkw;
    }

    // ---- per-thread parameter computation (8 modes) -----------------------
    u64 pw_re[4], pw_im[4], pw2_re[4], pw2_im[4], pnw2_im[4];
    u64 pccw_re[4], pnccw_im[4], pccw2_re[4], pnccw2_im[4];
    u64 xre2[4], xim2[4];
    float s0p = 0.0f, s1p = 0.0f;
    {
        float dt = expf(log_dt[h]);
        int base = h * Nq + sub * MPL;
#pragma unroll
        for (int p = 0; p < 4; p++) {
            float wreA[2], wimA[2], w2reA[2], w2imA[2];
            float cwreA[2], cwimA[2], cw2reA[2], cw2imA[2];
#pragma unroll
            for (int s = 0; s < 2; s++) {
                int idx = base + 2 * p + s;
                float ar = -expf(A_re[idx]);
                float ai = A_im[idx];
                float er = expf(dt * ar);
                float wre = er * cosf(dt * ai);
                float wim = er * sinf(dt * ai);
                float den = ar * ar + ai * ai;
                float numr = wre - 1.0f, numi = wim;
                float qre = (numr * ar + numi * ai) / den;
                float qim = (numi * ar - numr * ai) / den;
                float cr = C_re[idx], ci = C_im[idx];
                float ccre = 2.0f * (cr * qre - ci * qim);
                float ccim = 2.0f * (cr * qim + ci * qre);
                float ccwre = ccre * wre - ccim * wim;
                float ccwim = ccre * wim + ccim * wre;
                float w2re = wre * wre - wim * wim;
                float w2im = 2.0f * wre * wim;
                float ccw2re = ccwre * wre - ccwim * wim;
                float ccw2im = ccwre * wim + ccwim * wre;
                s0p += ccre;
                s1p += ccwre;
                wreA[s] = wre;   wimA[s] = wim;
                w2reA[s] = w2re; w2imA[s] = w2im;
                cwreA[s] = ccwre;  cwimA[s] = ccwim;
                cw2reA[s] = ccw2re; cw2imA[s] = ccw2im;
            }
            pw_re[p]     = pk2(wreA[0],  wreA[1]);
            pw_im[p]     = pk2(wimA[0],  wimA[1]);
            pw2_re[p]    = pk2(w2reA[0], w2reA[1]);
            pw2_im[p]    = pk2(w2imA[0], w2imA[1]);
            pnw2_im[p]   = pk2(-w2imA[0], -w2imA[1]);
            pccw_re[p]   = pk2(cwreA[0], cwreA[1]);
            pnccw_im[p]  = pk2(-cwimA[0], -cwimA[1]);
            pccw2_re[p]  = pk2(cw2reA[0], cw2reA[1]);
            pnccw2_im[p] = pk2(-cw2imA[0], -cw2imA[1]);
            xre2[p] = 0ull;
            xim2[p] = 0ull;
        }
    }
    // sum s0/s1 across the 8 lanes of this sequence
    s0p += __shfl_xor_sync(0xFFFFFFFFu, s0p, 1);
    s0p += __shfl_xor_sync(0xFFFFFFFFu, s0p, 2);
    s0p += __shfl_xor_sync(0xFFFFFFFFu, s0p, 4);
    s1p += __shfl_xor_sync(0xFFFFFFFFu, s1p, 1);
    s1p += __shfl_xor_sync(0xFFFFFFFFu, s1p, 2);
    s1p += __shfl_xor_sync(0xFFFFFFFFu, s1p, 4);
    float Ds0 = D[h] + s0p;
    float s1  = s1p;

    const float* ub = u + (size_t)gid0 * Lq;

    for (int c0 = 0; c0 < Lq; c0 += TCH) {
#pragma unroll
        for (int it = 0; it < (SEQS * TCH / 4) / 128; it++) {
            int idx = tid + it * 128;
            int r   = idx >> 6;
            int c4  = idx & 63;
            float4 v = *(const float4*)(ub + (size_t)r * Lq + c0 + c4 * 4);
            *(float4*)&su[r][c4 * 4] = v;
        }
        __syncthreads();

        for (int t0 = 0; t0 < TCH; t0 += 8) {
            u64 accA[4], accB[4];
            float usv[8];
            // ---- phase 1: 4 state/acc iterations (FMA2 only) ----
#pragma unroll
            for (int j = 0; j < 4; j++) {
                float us1 = su[grp][t0 + 2 * j];
                float us2 = su[grp][t0 + 2 * j + 1];
                usv[2 * j]     = us1;
                usv[2 * j + 1] = us2;
                u64 u1_2 = pk2(us1, us1);
                u64 u2_2 = pk2(us2, us2);
                u64 a = 0ull, b = 0ull;
#pragma unroll
                for (int p = 0; p < 4; p++) {
                    u64 tre = ffma2(pw_re[p], u1_2, u2_2);
                    tre = ffma2(pw2_re[p],  xre2[p], tre);
                    tre = ffma2(pnw2_im[p], xim2[p], tre);
                    u64 tim = fmul2(pw2_im[p], xre2[p]);
                    tim = ffma2(pw2_re[p], xim2[p], tim);
                    tim = ffma2(pw_im[p],  u1_2,    tim);
                    a = ffma2(pccw_re[p],   xre2[p], a);
                    a = ffma2(pnccw_im[p],  xim2[p], a);
                    b = ffma2(pccw2_re[p],  xre2[p], b);
                    b = ffma2(pnccw2_im[p], xim2[p], b);
                    xre2[p] = tre;
                    xim2[p] = tim;
                }
                accA[j] = a;
                accB[j] = b;
            }
            // ---- phase 2: 4 independent packed reduction trees ----
            float hold = 0.0f;
#pragma unroll
            for (int j = 0; j < 4; j++) {
                float2 ra = upk2(accA[j]);
                float2 rb = upk2(accB[j]);
                u64 c = pk2(ra.x + ra.y, rb.x + rb.y);
                c = fadd2(c, __shfl_xor_sync(0xFFFFFFFFu, c, 1));
                c = fadd2(c, __shfl_xor_sync(0xFFFFFFFFu, c, 2));
                c = fadd2(c, __shfl_xor_sync(0xFFFFFFFFu, c, 4));
                float2 f = upk2(c);
                float y1 = fmaf(Ds0, usv[2 * j], f.x);
                float y2 = fmaf(Ds0, usv[2 * j + 1], fmaf(s1, usv[2 * j], f.y));
                if (2 * j     == sub) hold = y1;
                if (2 * j + 1 == sub) hold = y2;
            }
            float gel = 0.5f * hold * (1.0f + erff(hold * 0.70710678118654752f));
            sy[grp][t0 + sub] = gel;
        }
        __syncthreads();

        // store activations as fp16
#pragma unroll
        for (int it = 0; it < (SEQS * TCH / 4) / 128; it++) {
            int idx = tid + it * 128;
            int r   = idx >> 6;
            int c4  = idx & 63;
            float4 v = *(float4*)&sy[r][c4 * 4];
            __half2 p0 = __floats2half2_rn(v.x, v.y);
            __half2 p1 = __floats2half2_rn(v.z, v.w);
            uint2 pk;
            pk.x = *(unsigned*)&p0;
            pk.y = *(unsigned*)&p1;
            size_t off = (size_t)(gid0 + r) * Lq + c0 + c4 * 4;
            *(uint2*)(g_yf + off) = pk;
        }
        __syncthreads();
    }
}

// ---------------- kernel 2: fp16 1-term GEMM, GBK=64, 2-stage pipeline -----
// out[b] (512 x 2048) = W (512x512) @ Y[b] (512x2048) + bias
#define GBM 128
#define GBN 128
#define GBK 64
#define ASTR 72
#define BSTR 136
#define A_ELEMS (GBM * ASTR)
#define B_ELEMS (GBK * BSTR)
#define AOFF(st) ((st) * A_ELEMS * 2)
#define BOFF(st) (2 * A_ELEMS * 2 + (st) * B_ELEMS * 2)
#define SMEM_GEMM (2 * A_ELEMS * 2 + 2 * B_ELEMS * 2)

#define LDSM4(r0, r1, r2, r3, addr) \
    asm volatile("ldmatrix.sync.aligned.m8n8.x4.shared.b16 {%0,%1,%2,%3},[%4];" \
                 : "=r"(r0), "=r"(r1), "=r"(r2), "=r"(r3) : "r"(addr))
#define LDSM4T(r0, r1, r2, r3, addr) \
    asm volatile("ldmatrix.sync.aligned.m8n8.x4.trans.shared.b16 {%0,%1,%2,%3},[%4];" \
                 : "=r"(r0), "=r"(r1), "=r"(r2), "=r"(r3) : "r"(addr))
#define MMA16816(d, a, b0, b1) \
    asm volatile("mma.sync.aligned.m16n8k16.row.col.f32.f16.f16.f32 " \
                 "{%0,%1,%2,%3},{%4,%5,%6,%7},{%8,%9},{%0,%1,%2,%3};" \
                 : "+f"(d[0]), "+f"(d[1]), "+f"(d[2]), "+f"(d[3]) \
                 : "r"(a[0]), "r"(a[1]), "r"(a[2]), "r"(a[3]), "r"(b0), "r"(b1))
#define CPA16(dst, src) \
    asm volatile("cp.async.cg.shared.global [%0],[%1],16;" :: "r"(dst), "l"(src))

extern __shared__ char dsm[];

__device__ __forceinline__ unsigned smem_u32g(const void* p) {
    unsigned a;
    asm("{ .reg .u64 t; cvta.to.shared.u64 t, %1; cvt.u32.u64 %0, t; }"
        : "=r"(a) : "l"(p));
    return a;
}

__global__ __launch_bounds__(256, 2) void gemm_kernel(const float* __restrict__ bias,
                                                      float* __restrict__ out) {
    unsigned sb = smem_u32g(dsm);
    int b   = blockIdx.z;
    int v0  = blockIdx.y * GBM;
    int l0  = blockIdx.x * GBN;
    int tid = threadIdx.x;
    int lane = tid & 31;
    int wid  = tid >> 5;
    int wm = wid >> 1;
    int wn = wid & 1;

    float acc[2][8][4];
#pragma unroll
    for (int i = 0; i < 2; i++)
#pragma unroll
        for (int j = 0; j < 8; j++)
#pragma unroll
            for (int k = 0; k < 4; k++) acc[i][j][k] = 0.0f;

#define LOAD_TILE(k0, st) do {                                              \
    _Pragma("unroll")                                                       \
    for (int q = 0; q < 4; q++) {                                           \
        int idx = tid + q * 256;                                            \
        int r = idx >> 3, c = (idx & 7) * 8;                                \
        size_t src = (size_t)(v0 + r) * Hq + (k0) + c;                      \
        unsigned d = (unsigned)(r * ASTR + c) * 2;                          \
        CPA16(sb + AOFF(st) + d, g_Wh + src);                               \
    }                                                                       \
    _Pragma("unroll")                                                       \
    for (int q = 0; q < 4; q++) {                                           \
        int idx = tid + q * 256;                                            \
        int r = idx >> 4, c = (idx & 15) * 8;                               \
        size_t src = (size_t)(b * Hq + (k0) + r) * Lq + l0 + c;             \
        unsigned d = (unsigned)(r * BSTR + c) * 2;                          \
        CPA16(sb + BOFF(st) + d, g_yf + src);                               \
    }                                                                       \
} while (0)

    LOAD_TILE(0, 0);
    asm volatile("cp.async.commit_group;");
    LOAD_TILE(GBK, 1);
    asm volatile("cp.async.commit_group;");

    for (int ch = 0; ch < Hq / GBK; ch++) {
        int st = ch & 1;
        asm volatile("cp.async.wait_group 1;");
        __syncthreads();

        unsigned ah_base = sb + AOFF(st);
        unsigned bh_base = sb + BOFF(st);

#pragma unroll
        for (int ks = 0; ks < 4; ks++) {
            unsigned ah[2][4], bh[4][4];
#pragma unroll
            for (int mf = 0; mf < 2; mf++) {
                unsigned d = ((wm * 32 + mf * 16 + (lane & 15)) * ASTR
                              + ks * 16 + (lane >> 4) * 8) * 2;
                LDSM4(ah[mf][0], ah[mf][1], ah[mf][2], ah[mf][3], ah_base + d);
            }
#pragma unroll
            for (int j = 0; j < 4; j++) {
                unsigned d = ((ks * 16 + (lane & 15)) * BSTR
                              + wn * 64 + j * 16 + (lane >> 4) * 8) * 2;
                LDSM4T(bh[j][0], bh[j][1], bh[j][2], bh[j][3], bh_base + d);
            }
#pragma unroll
            for (int mf = 0; mf < 2; mf++)
#pragma unroll
                for (int n8 = 0; n8 < 8; n8++) {
                    int j = n8 >> 1, hi = (n8 & 1) * 2;
                    MMA16816(acc[mf][n8], ah[mf], bh[j][hi], bh[j][hi + 1]);
                }
        }
        __syncthreads();

        int knext = (ch + 2) * GBK;
        if (knext < Hq) {
            LOAD_TILE(knext, st);
        }
        asm volatile("cp.async.commit_group;");
    }

    // ---- epilogue: bias + store ----
    int tq = lane >> 2, tr = lane & 3;
#pragma unroll
    for (int mf = 0; mf < 2; mf++) {
        int v = v0 + wm * 32 + mf * 16 + tq;
        float bv0 = bias[v], bv1 = bias[v + 8];
#pragma unroll
        for (int n8 = 0; n8 < 8; n8++) {
            int l = l0 + wn * 64 + n8 * 8 + tr * 2;
            float2 s0, s1;
            s0.x = acc[mf][n8][0] + bv0; s0.y = acc[mf][n8][1] + bv0;
            s1.x = acc[mf][n8][2] + bv1; s1.y = acc[mf][n8][3] + bv1;
            *(float2*)(out + ((size_t)b * Hq + v) * Lq + l)     = s0;
            *(float2*)(out + ((size_t)b * Hq + v + 8) * Lq + l) = s1;
        }
    }
}

// ---------------- launch ----------------------------------------------------
extern "C" void kernel_launch(void* const* d_in, const int* in_sizes, int n_in,
                              void* d_out, int out_size) {
    (void)in_sizes; (void)n_in; (void)out_size;
    const float* u      = (const float*)d_in[0];
    const float* log_dt = (const float*)d_in[1];
    const float* A_re   = (const float*)d_in[2];
    const float* A_im   = (const float*)d_in[3];
    const float* C_re   = (const float*)d_in[4];
    const float* C_im   = (const float*)d_in[5];
    const float* D      = (const float*)d_in[6];
    const float* W      = (const float*)d_in[7];
    const float* bias   = (const float*)d_in[8];
    float* out = (float*)d_out;

    static int smem_set = 0;
    if (!smem_set) {
        cudaFuncSetAttribute(gemm_kernel,
                             cudaFuncAttributeMaxDynamicSharedMemorySize,
                             SMEM_GEMM);
        smem_set = 1;
    }

    scan_kernel<<<Bq * Hq / SEQS, 128>>>(u, D, log_dt, A_re, A_im, C_re, C_im, W);
    dim3 g(Lq / GBN, Hq / GBM, Bq);
    gemm_kernel<<<g, 256, SMEM_GEMM>>>(bias, out);
}